// round 5
// baseline (speedup 1.0000x reference)
#include <cuda_runtime.h>
#include <cuda_bf16.h>
#include <stdint.h>
#include <math.h>

#define BB   8
#define NN   4096
#define DD   64
#define KNN  20
#define OO   64

// ---------------- scratch (__device__ globals: allocation-free) ----------------
__device__ float g_sq[BB*NN];
__device__ float g_y [BB*NN*OO];
__device__ float g_z [BB*NN*OO];
__device__ int   g_idx[BB*NN*KNN];
__device__ float g_h [BB*NN*OO];
__device__ float g_psum[128*OO];
__device__ float g_psq [128*OO];
__device__ float g_a [OO];
__device__ float g_bb2[OO];
// bf16x3 split layouts, k-major per point, K=192:
//   A' = [hi | lo | hi]   B' = [hi | hi | lo]   (dot(A',B') = hh + lh + hl)
__device__ __nv_bfloat16 g_xa[(size_t)BB*NN*192];
__device__ __nv_bfloat16 g_xb[(size_t)BB*NN*192];

__device__ __forceinline__ uint32_t smem_u32(const void* p) {
    uint32_t a;
    asm("{ .reg .u64 t; cvta.to.shared.u64 t, %1; cvt.u32.u64 %0, t; }" : "=r"(a) : "l"(p));
    return a;
}
__device__ __forceinline__ uint32_t pack_bf2(__nv_bfloat16 a, __nv_bfloat16 b) {
    return (uint32_t)__bfloat16_as_ushort(a) | ((uint32_t)__bfloat16_as_ushort(b) << 16);
}
__device__ __forceinline__ void cp16(uint32_t dst, const void* src) {
    asm volatile("cp.async.ca.shared.global [%0], [%1], 16;" :: "r"(dst), "l"(src) : "memory");
}
#define CP_COMMIT() asm volatile("cp.async.commit_group;" ::: "memory")
#define CP_WAIT0()  asm volatile("cp.async.wait_group 0;" ::: "memory")
#define CP_WAIT1()  asm volatile("cp.async.wait_group 1;" ::: "memory")

// sortable-uint packing for float criterion
__device__ __forceinline__ uint32_t f2sort(float c) {
    uint32_t u = __float_as_uint(c);
    return u ^ ((uint32_t)((int)u >> 31) | 0x80000000u);
}
__device__ __forceinline__ float sort2f(uint32_t s) {
    uint32_t u = s ^ ((uint32_t)((int)(~s) >> 31) | 0x80000000u);
    return __uint_as_float(u);
}

// argmax over 20 packed u64 (tree, 19 combines)
__device__ __forceinline__ void argmax20(const uint64_t (&lst)[KNN],
                                         uint64_t &wm, int &wp)
{
    uint64_t v[10]; int p[10];
    #pragma unroll
    for (int j = 0; j < 10; j++) {
        bool g = lst[2*j+1] > lst[2*j];
        v[j] = g ? lst[2*j+1] : lst[2*j];
        p[j] = g ? 2*j+1 : 2*j;
    }
    #pragma unroll
    for (int j = 0; j < 5; j++) {
        bool g = v[j+5] > v[j];
        v[j] = g ? v[j+5] : v[j];
        p[j] = g ? p[j+5] : p[j];
    }
    bool g0 = v[1] > v[0]; uint64_t va = g0 ? v[1] : v[0]; int pa = g0 ? p[1] : p[0];
    bool g1 = v[3] > v[2]; uint64_t vb = g1 ? v[3] : v[2]; int pb = g1 ? p[3] : p[2];
    bool g2 = vb > va;     va = g2 ? vb : va;              pa = g2 ? pb : pa;
    bool g3 = v[4] > va;   va = g3 ? v[4] : va;            pa = g3 ? p[4] : pa;
    wm = va; wp = pa;
}

// unsorted top-20, max-replacement insert (cheap divergent path)
__device__ __forceinline__ void tk_insert(uint64_t (&lst)[KNN], float &wmaxf, int &wpos,
                                          float c, int m)
{
    if (c < wmaxf) {
        lst[wpos] = ((uint64_t)f2sort(c) << 32) | (uint32_t)m;
        uint64_t wm; int wp;
        argmax20(lst, wm, wp);
        wpos = wp;
        wmaxf = sort2f((uint32_t)(wm >> 32));
    }
}

// ---------------- kernel 1: sumsq, y, z, and bf16x3 split layouts --------------
__global__ __launch_bounds__(128) void prep_kernel(const float* __restrict__ x,
                                                   const float* __restrict__ w)
{
    __shared__ float ws[64*128];
    int tid = threadIdx.x;
    #pragma unroll
    for (int i = 0; i < 64; i++) ws[i*128 + tid] = w[i*128 + tid];
    __syncthreads();

    int b = blockIdx.y;
    int n = blockIdx.x * 128 + tid;
    const float* xb = x + b * (DD*NN);

    float p[DD];
    float sq = 0.f;
    #pragma unroll
    for (int d = 0; d < DD; d++) { p[d] = xb[d*NN + n]; sq = fmaf(p[d], p[d], sq); }
    g_sq[b*NN + n] = sq;

    uint4* pa = (uint4*)(g_xa + (size_t)(b*NN + n)*192);
    uint4* pb = (uint4*)(g_xb + (size_t)(b*NN + n)*192);
    #pragma unroll
    for (int d = 0; d < DD; d += 8) {
        uint32_t hv[4], lv[4];
        #pragma unroll
        for (int j = 0; j < 4; j++) {
            float v0 = p[d + 2*j], v1 = p[d + 2*j + 1];
            __nv_bfloat16 h0 = __float2bfloat16(v0);
            __nv_bfloat16 h1 = __float2bfloat16(v1);
            __nv_bfloat16 l0 = __float2bfloat16(v0 - __bfloat162float(h0));
            __nv_bfloat16 l1 = __float2bfloat16(v1 - __bfloat162float(h1));
            hv[j] = pack_bf2(h0, h1);
            lv[j] = pack_bf2(l0, l1);
        }
        uint4 H = make_uint4(hv[0], hv[1], hv[2], hv[3]);
        uint4 L = make_uint4(lv[0], lv[1], lv[2], lv[3]);
        int c = d >> 3;
        pa[c] = H; pa[8 + c] = L; pa[16 + c] = H;
        pb[c] = H; pb[8 + c] = H; pb[16 + c] = L;
    }

    float* yp = g_y + (b*NN + n)*OO;
    float* zp = g_z + (b*NN + n)*OO;
    #pragma unroll 2
    for (int o = 0; o < OO; o += 4) {
        float ya[4], za[4];
        #pragma unroll
        for (int j = 0; j < 4; j++) { ya[j] = 0.f; za[j] = 0.f; }
        #pragma unroll
        for (int d = 0; d < DD; d++) {
            float pd = p[d];
            #pragma unroll
            for (int j = 0; j < 4; j++) {
                float w1 = ws[(o+j)*128 + d];
                float w2 = ws[(o+j)*128 + 64 + d];
                ya[j] = fmaf(pd, w1, ya[j]);
                za[j] = fmaf(pd, w2 - w1, za[j]);
            }
        }
        *(float4*)&yp[o] = make_float4(ya[0], ya[1], ya[2], ya[3]);
        *(float4*)&zp[o] = make_float4(za[0], za[1], za[2], za[3]);
    }
}

// ---------------- kernel 2: HMMA Gram + cp.async pipeline + top-20 -------------
// smem layout: bf16 tiles use 400B row stride (conflict-free ldmatrix)
#define SM_A   0
#define SM_B0  51200
#define SM_B1  102400
#define SM_SQ  153600            // float sqs[2][128]
#define SM_D   154624            // float sD[128][130]; aliased as u64 lists after loop
#define SM_TOT 221184

__global__ __launch_bounds__(256, 1) void knn_kernel()
{
    extern __shared__ char smem[];
    const uint32_t sb = smem_u32(smem);
    float* sD  = (float*)(smem + SM_D);
    float* sqs = (float*)(smem + SM_SQ);

    const int tid  = threadIdx.x;
    const int lane = tid & 31;
    const int w    = tid >> 5;
    const int b    = blockIdx.y;
    const int r0   = blockIdx.x * 128;

    // A' rows r0..r0+127 (384B/row) -> smem (400B/row), plain copy
    {
        const char* ga = (const char*)(g_xa + (size_t)(b*NN + r0)*192);
        #pragma unroll 4
        for (int i = tid; i < 128*24; i += 256) {
            int p = i / 24, c = i % 24;
            *(uint4*)(smem + SM_A + p*400 + c*16) = *(const uint4*)(ga + p*384 + c*16);
        }
    }
    // issue async copy of B tile 0 + sq 0
    {
        const char* gb = (const char*)(g_xb + (size_t)(b*NN)*192);
        #pragma unroll 4
        for (int i = tid; i < 128*24; i += 256) {
            int p = i / 24, c = i % 24;
            cp16(sb + SM_B0 + (uint32_t)(p*400 + c*16), gb + p*384 + c*16);
        }
        if (tid < 32) cp16(sb + SM_SQ + (uint32_t)(tid*16), (const char*)(g_sq + b*NN + tid*4));
        CP_COMMIT();
    }

    // per-thread unsorted top-20 (order irrelevant downstream: max-pool)
    uint64_t lst[KNN];
    #pragma unroll
    for (int j = 0; j < KNN; j++) lst[j] = (0xFF7FFFFFull << 32) | (uint32_t)j;
    float wmaxf = 3.4e38f;
    int   wpos  = 0;

    const int half  = tid >> 7;          // 0 or 1
    const int srow  = tid & 127;
    const int cbase = half * 64;

    // ldmatrix lane addressing
    const int mm = lane >> 3, rr = lane & 7;
    const uint32_t aaddr0 = sb + SM_A
        + (uint32_t)((w*16 + ((mm & 1) << 3) + rr) * 400)
        + (uint32_t)(((mm & 2) ? 8 : 0) * 2);
    const uint32_t baddr_row = (uint32_t)((((mm & 2) ? 8 : 0) + rr) * 400)
                             + (uint32_t)(((mm & 1) ? 8 : 0) * 2);

    for (int t = 0; t < 32; t++) {
        const int cur = t & 1;
        const int nxt = cur ^ 1;
        const int m0  = t * 128;

        // prefetch B tile t+1 into the other buffer (async, overlapped)
        if (t + 1 < 32) {
            const int mn = m0 + 128;
            const char* gb = (const char*)(g_xb + (size_t)(b*NN + mn)*192);
            const uint32_t bdst = sb + (nxt ? SM_B1 : SM_B0);
            #pragma unroll 4
            for (int i = tid; i < 128*24; i += 256) {
                int p = i / 24, c = i % 24;
                cp16(bdst + (uint32_t)(p*400 + c*16), gb + p*384 + c*16);
            }
            if (tid < 32) cp16(sb + SM_SQ + (uint32_t)(nxt*512 + tid*16),
                               (const char*)(g_sq + b*NN + mn + tid*4));
            CP_COMMIT();
            CP_WAIT1();          // tile t's copy done; t+1 may still be in flight
        } else {
            CP_WAIT0();
        }
        __syncthreads();

        // MMA: 16 rows (this warp) x 128 cols, K = 192
        float acc[16][4];
        #pragma unroll
        for (int i = 0; i < 16; i++)
            #pragma unroll
            for (int j = 0; j < 4; j++) acc[i][j] = 0.f;

        const uint32_t bbase = sb + (cur ? SM_B1 : SM_B0) + baddr_row;
        #pragma unroll 2
        for (int ks = 0; ks < 12; ks++) {
            uint32_t a0, a1, a2, a3;
            asm volatile("ldmatrix.sync.aligned.m8n8.x4.shared.b16 {%0,%1,%2,%3}, [%4];"
                : "=r"(a0), "=r"(a1), "=r"(a2), "=r"(a3)
                : "r"(aaddr0 + (uint32_t)(ks*32)));
            const uint32_t bbk = bbase + (uint32_t)(ks*32);
            #pragma unroll
            for (int ct = 0; ct < 8; ct++) {
                uint32_t b0, b1, b2, b3;
                asm volatile("ldmatrix.sync.aligned.m8n8.x4.shared.b16 {%0,%1,%2,%3}, [%4];"
                    : "=r"(b0), "=r"(b1), "=r"(b2), "=r"(b3)
                    : "r"(bbk + (uint32_t)(ct*16*400)));
                asm volatile("mma.sync.aligned.m16n8k16.row.col.f32.bf16.bf16.f32 "
                    "{%0,%1,%2,%3},{%4,%5,%6,%7},{%8,%9},{%0,%1,%2,%3};"
                    : "+f"(acc[2*ct][0]), "+f"(acc[2*ct][1]),
                      "+f"(acc[2*ct][2]), "+f"(acc[2*ct][3])
                    : "r"(a0), "r"(a1), "r"(a2), "r"(a3), "r"(b0), "r"(b1));
                asm volatile("mma.sync.aligned.m16n8k16.row.col.f32.bf16.bf16.f32 "
                    "{%0,%1,%2,%3},{%4,%5,%6,%7},{%8,%9},{%0,%1,%2,%3};"
                    : "+f"(acc[2*ct+1][0]), "+f"(acc[2*ct+1][1]),
                      "+f"(acc[2*ct+1][2]), "+f"(acc[2*ct+1][3])
                    : "r"(a0), "r"(a1), "r"(a2), "r"(a3), "r"(b2), "r"(b3));
            }
        }

        // stage criterion = sq[m] - 2*dot
        {
            const int rw = w*16 + (lane >> 2);
            const int cb = (lane & 3) * 2;
            const float* sqc = sqs + cur*128;
            #pragma unroll
            for (int i = 0; i < 16; i++) {
                int col = i*8 + cb;
                float s0 = sqc[col], s1 = sqc[col+1];
                *(float2*)&sD[rw*130 + col] =
                    make_float2(fmaf(-2.f, acc[i][0], s0), fmaf(-2.f, acc[i][1], s1));
                *(float2*)&sD[(rw+8)*130 + col] =
                    make_float2(fmaf(-2.f, acc[i][2], s0), fmaf(-2.f, acc[i][3], s1));
            }
        }
        __syncthreads();

        // scan: thread owns half a row
        {
            const float* row = &sD[srow*130 + cbase];
            const int mb = m0 + cbase;
            #pragma unroll 4
            for (int c = 0; c < 64; c++)
                tk_insert(lst, wmaxf, wpos, row[c], mb + c);
        }
        __syncthreads();
    }

    // merge the two per-row half-lists (both unsorted; select 20 smallest of 40)
    uint64_t* ml = (uint64_t*)sD;
    #pragma unroll
    for (int j = 0; j < KNN; j++) ml[tid*KNN + j] = lst[j];
    __syncthreads();
    if (tid < 128) {
        const uint64_t* la = ml + (size_t)tid*KNN;
        const uint64_t* lb = ml + (size_t)(tid + 128)*KNN;
        uint64_t nl[KNN];
        #pragma unroll
        for (int j = 0; j < KNN; j++) nl[j] = la[j];
        uint64_t wm; int wp;
        argmax20(nl, wm, wp);
        #pragma unroll
        for (int j = 0; j < KNN; j++) {
            uint64_t cd = lb[j];
            if (cd < wm) { nl[wp] = cd; argmax20(nl, wm, wp); }
        }
        int* op = g_idx + (b*NN + r0 + tid)*KNN;
        #pragma unroll
        for (int j = 0; j < KNN; j++) op[j] = (int)(uint32_t)nl[j];
    }
}

// ---------------- kernel 3: gather-max + h + BN partial sums -------------------
__global__ __launch_bounds__(256) void hmax_kernel()
{
    int tid = threadIdx.x;
    int warp = tid >> 5, lane = tid & 31;
    int b = blockIdx.y;
    int nbase = blockIdx.x * 256 + warp * 32;
    const float* yb = g_y + b*NN*OO;

    float s0 = 0.f, s1 = 0.f, q0 = 0.f, q1 = 0.f;
    for (int i = 0; i < 32; i++) {
        int n = nbase + i;
        const int* ip = g_idx + (b*NN + n)*KNN;
        float m0v = -3.4e38f, m1v = -3.4e38f;
        #pragma unroll
        for (int k = 0; k < KNN; k++) {
            int m = ip[k];
            const float* yr = yb + m*OO;
            m0v = fmaxf(m0v, yr[lane]);
            m1v = fmaxf(m1v, yr[lane + 32]);
        }
        const float* zr = g_z + (b*NN + n)*OO;
        float h0 = zr[lane]      + m0v;
        float h1 = zr[lane + 32] + m1v;
        g_h[(b*NN + n)*OO + lane]      = h0;
        g_h[(b*NN + n)*OO + lane + 32] = h1;
        s0 += h0; s1 += h1;
        q0 = fmaf(h0, h0, q0); q1 = fmaf(h1, h1, q1);
    }

    __shared__ float ps[8][64], pq[8][64];
    ps[warp][lane]      = s0; ps[warp][lane + 32] = s1;
    pq[warp][lane]      = q0; pq[warp][lane + 32] = q1;
    __syncthreads();
    if (tid < 64) {
        float S = 0.f, Q = 0.f;
        #pragma unroll
        for (int wr = 0; wr < 8; wr++) { S += ps[wr][tid]; Q += pq[wr][tid]; }
        int blk = b*16 + blockIdx.x;
        g_psum[blk*64 + tid] = S;
        g_psq [blk*64 + tid] = Q;
    }
}

// ---------------- kernel 4: deterministic fp64 stats reduce --------------------
__global__ __launch_bounds__(1024) void stats_kernel(const float* __restrict__ gamma,
                                                     const float* __restrict__ beta)
{
    __shared__ double sS[1024], sQ[1024];
    int ch = threadIdx.x & 63;
    int sl = threadIdx.x >> 6;        // 16 slices per channel
    double S = 0.0, Q = 0.0;
    #pragma unroll
    for (int i = sl; i < 128; i += 16) {
        S += (double)g_psum[i*64 + ch];
        Q += (double)g_psq [i*64 + ch];
    }
    sS[threadIdx.x] = S; sQ[threadIdx.x] = Q;
    __syncthreads();
    if (sl == 0) {
        double St = 0.0, Qt = 0.0;
        #pragma unroll
        for (int k = 0; k < 16; k++) { St += sS[k*64 + ch]; Qt += sQ[k*64 + ch]; }
        double cnt  = (double)(BB * NN);
        double mean = St / cnt;
        double var  = Qt / cnt - mean * mean;
        float inv = (float)(1.0 / sqrt(var + 1e-5));
        float a = gamma[ch] * inv;
        g_a  [ch] = a;
        g_bb2[ch] = beta[ch] - (float)mean * a;
    }
}

// ---------------- kernel 5: BN affine + exact GELU + transpose -----------------
__global__ __launch_bounds__(256) void final_kernel(float* __restrict__ out)
{
    __shared__ float t[64][65];
    int tid = threadIdx.x;
    int b = blockIdx.y;
    int n0 = blockIdx.x * 64;
    const float* hb = g_h + b*NN*OO;

    #pragma unroll
    for (int it = 0; it < 16; it++) {
        int idx = it*256 + tid;
        int nl = idx >> 6, o = idx & 63;
        t[nl][o] = hb[(n0 + nl)*OO + o];
    }
    __syncthreads();

    float* ob = out + b*OO*NN;
    #pragma unroll
    for (int it = 0; it < 16; it++) {
        int idx = it*256 + tid;
        int o = idx >> 6, nl = idx & 63;
        float v = t[nl][o] * g_a[o] + g_bb2[o];
        ob[o*NN + n0 + nl] = 0.5f * v * (1.f + erff(v * 0.70710678118654752f));
    }
}

// ---------------- launch --------------------------------------------------------
extern "C" void kernel_launch(void* const* d_in, const int* in_sizes, int n_in,
                              void* d_out, int out_size)
{
    const float* x     = (const float*)d_in[0];
    const float* w     = (const float*)d_in[1];
    const float* gamma = (const float*)d_in[2];
    const float* beta  = (const float*)d_in[3];
    float* out = (float*)d_out;

    cudaFuncSetAttribute(knn_kernel, cudaFuncAttributeMaxDynamicSharedMemorySize, SM_TOT);

    prep_kernel <<<dim3(NN/128, BB), 128>>>(x, w);
    knn_kernel  <<<dim3(NN/128, BB), 256, SM_TOT>>>();
    hmax_kernel <<<dim3(NN/256, BB), 256>>>();
    stats_kernel<<<1, 1024>>>(gamma, beta);
    final_kernel<<<dim3(NN/64, BB), 256>>>(out);
}

// round 6
// speedup vs baseline: 1.5918x; 1.5918x over previous
#include <cuda_runtime.h>
#include <cuda_bf16.h>
#include <stdint.h>
#include <math.h>

#define BB   8
#define NN   4096
#define DD   64
#define KNN  20
#define OO   64

// ---------------- scratch (__device__ globals: allocation-free) ----------------
__device__ float g_sq[BB*NN];
__device__ float g_y [BB*NN*OO];
__device__ float g_z [BB*NN*OO];
__device__ int   g_idx[BB*NN*KNN];
__device__ float g_h [BB*NN*OO];
__device__ float g_psum[128*OO];
__device__ float g_psq [128*OO];
__device__ float g_a [OO];
__device__ float g_bb2[OO];
// bf16x3 split layouts, k-major per point, K=192:
//   A' = [hi | lo | hi]   B' = [hi | hi | lo]   (dot(A',B') = hh + lh + hl)
__device__ __nv_bfloat16 g_xa[(size_t)BB*NN*192];
__device__ __nv_bfloat16 g_xb[(size_t)BB*NN*192];

__device__ __forceinline__ uint32_t smem_u32(const void* p) {
    uint32_t a;
    asm("{ .reg .u64 t; cvta.to.shared.u64 t, %1; cvt.u32.u64 %0, t; }" : "=r"(a) : "l"(p));
    return a;
}
__device__ __forceinline__ uint32_t pack_bf2(__nv_bfloat16 a, __nv_bfloat16 b) {
    return (uint32_t)__bfloat16_as_ushort(a) | ((uint32_t)__bfloat16_as_ushort(b) << 16);
}
__device__ __forceinline__ void cp16(uint32_t dst, const void* src) {
    asm volatile("cp.async.ca.shared.global [%0], [%1], 16;" :: "r"(dst), "l"(src) : "memory");
}
#define CP_COMMIT() asm volatile("cp.async.commit_group;" ::: "memory")
#define CP_WAIT0()  asm volatile("cp.async.wait_group 0;" ::: "memory")
#define CP_WAIT1()  asm volatile("cp.async.wait_group 1;" ::: "memory")

// ---------------- kernel 1: sumsq, y, z, and bf16x3 split layouts --------------
__global__ __launch_bounds__(128) void prep_kernel(const float* __restrict__ x,
                                                   const float* __restrict__ w)
{
    __shared__ float ws[64*128];
    int tid = threadIdx.x;
    #pragma unroll
    for (int i = 0; i < 64; i++) ws[i*128 + tid] = w[i*128 + tid];
    __syncthreads();

    int b = blockIdx.y;
    int n = blockIdx.x * 128 + tid;
    const float* xb = x + b * (DD*NN);

    float p[DD];
    float sq = 0.f;
    #pragma unroll
    for (int d = 0; d < DD; d++) { p[d] = xb[d*NN + n]; sq = fmaf(p[d], p[d], sq); }
    g_sq[b*NN + n] = sq;

    uint4* pa = (uint4*)(g_xa + (size_t)(b*NN + n)*192);
    uint4* pb = (uint4*)(g_xb + (size_t)(b*NN + n)*192);
    #pragma unroll
    for (int d = 0; d < DD; d += 8) {
        uint32_t hv[4], lv[4];
        #pragma unroll
        for (int j = 0; j < 4; j++) {
            float v0 = p[d + 2*j], v1 = p[d + 2*j + 1];
            __nv_bfloat16 h0 = __float2bfloat16(v0);
            __nv_bfloat16 h1 = __float2bfloat16(v1);
            __nv_bfloat16 l0 = __float2bfloat16(v0 - __bfloat162float(h0));
            __nv_bfloat16 l1 = __float2bfloat16(v1 - __bfloat162float(h1));
            hv[j] = pack_bf2(h0, h1);
            lv[j] = pack_bf2(l0, l1);
        }
        uint4 H = make_uint4(hv[0], hv[1], hv[2], hv[3]);
        uint4 L = make_uint4(lv[0], lv[1], lv[2], lv[3]);
        int c = d >> 3;
        pa[c] = H; pa[8 + c] = L; pa[16 + c] = H;
        pb[c] = H; pb[8 + c] = H; pb[16 + c] = L;
    }

    float* yp = g_y + (b*NN + n)*OO;
    float* zp = g_z + (b*NN + n)*OO;
    #pragma unroll 2
    for (int o = 0; o < OO; o += 4) {
        float ya[4], za[4];
        #pragma unroll
        for (int j = 0; j < 4; j++) { ya[j] = 0.f; za[j] = 0.f; }
        #pragma unroll
        for (int d = 0; d < DD; d++) {
            float pd = p[d];
            #pragma unroll
            for (int j = 0; j < 4; j++) {
                float w1 = ws[(o+j)*128 + d];
                float w2 = ws[(o+j)*128 + 64 + d];
                ya[j] = fmaf(pd, w1, ya[j]);
                za[j] = fmaf(pd, w2 - w1, za[j]);
            }
        }
        *(float4*)&yp[o] = make_float4(ya[0], ya[1], ya[2], ya[3]);
        *(float4*)&zp[o] = make_float4(za[0], za[1], za[2], za[3]);
    }
}

// ---------------- kernel 2: HMMA Gram + cp.async pipeline + top-20 -------------
__device__ __forceinline__ void topk_insert(float (&best)[KNN], int (&bidx)[KNN],
                                            float c, int m)
{
    if (c < best[KNN-1]) {
        best[KNN-1] = c; bidx[KNN-1] = m;
        #pragma unroll
        for (int t = KNN-1; t > 0; --t) {
            if (best[t-1] > best[t]) {
                float tf = best[t-1]; best[t-1] = best[t]; best[t] = tf;
                int   ti = bidx[t-1]; bidx[t-1] = bidx[t]; bidx[t] = ti;
            }
        }
    }
}

// smem layout: bf16 tiles use 400B row stride (conflict-free ldmatrix)
#define SM_A   0
#define SM_B0  51200
#define SM_B1  102400
#define SM_SQ  153600            // float sqs[2][128]
#define SM_D   154624            // float sD[128][130]; aliased for merge lists
#define SM_TOT 221184

__global__ __launch_bounds__(256, 1) void knn_kernel()
{
    extern __shared__ char smem[];
    const uint32_t sb = smem_u32(smem);
    float* sD  = (float*)(smem + SM_D);
    float* sqs = (float*)(smem + SM_SQ);

    const int tid  = threadIdx.x;
    const int lane = tid & 31;
    const int w    = tid >> 5;
    const int b    = blockIdx.y;
    const int r0   = blockIdx.x * 128;

    // issue async copy of B tile 0 + sq 0 first (deepest prefetch)
    {
        const char* gb = (const char*)(g_xb + (size_t)(b*NN)*192);
        #pragma unroll 4
        for (int i = tid; i < 128*24; i += 256) {
            int p = i / 24, c = i % 24;
            cp16(sb + SM_B0 + (uint32_t)(p*400 + c*16), gb + p*384 + c*16);
        }
        if (tid < 32) cp16(sb + SM_SQ + (uint32_t)(tid*16), (const char*)(g_sq + b*NN + tid*4));
        CP_COMMIT();
    }
    // A' rows r0..r0+127 (384B/row) -> smem (400B/row), plain copy (overlaps cp.async)
    {
        const char* ga = (const char*)(g_xa + (size_t)(b*NN + r0)*192);
        #pragma unroll 4
        for (int i = tid; i < 128*24; i += 256) {
            int p = i / 24, c = i % 24;
            *(uint4*)(smem + SM_A + p*400 + c*16) = *(const uint4*)(ga + p*384 + c*16);
        }
    }

    float best[KNN];
    int   bidx[KNN];
    #pragma unroll
    for (int j = 0; j < KNN; j++) { best[j] = 3.4e38f; bidx[j] = 0; }

    const int half  = tid >> 7;          // 0 or 1
    const int srow  = tid & 127;
    const int cbase = half * 64;

    // ldmatrix lane addressing: mm = matrix index (l>>3), rr = l&7
    const int mm = lane >> 3, rr = lane & 7;
    const uint32_t aaddr0 = sb + SM_A
        + (uint32_t)((w*16 + ((mm & 1) << 3) + rr) * 400)
        + (uint32_t)(((mm & 2) ? 8 : 0) * 2);
    const uint32_t baddr_row = (uint32_t)((((mm & 2) ? 8 : 0) + rr) * 400)
                             + (uint32_t)(((mm & 1) ? 8 : 0) * 2);

    for (int t = 0; t < 32; t++) {
        const int cur = t & 1;
        const int nxt = cur ^ 1;
        const int m0  = t * 128;

        // prefetch B tile t+1 + sq into the other buffer (async, overlapped)
        if (t + 1 < 32) {
            const int mn = m0 + 128;
            const char* gb = (const char*)(g_xb + (size_t)(b*NN + mn)*192);
            const uint32_t bdst = sb + (nxt ? SM_B1 : SM_B0);
            #pragma unroll 4
            for (int i = tid; i < 128*24; i += 256) {
                int p = i / 24, c = i % 24;
                cp16(bdst + (uint32_t)(p*400 + c*16), gb + p*384 + c*16);
            }
            if (tid < 32) cp16(sb + SM_SQ + (uint32_t)(nxt*512 + tid*16),
                               (const char*)(g_sq + b*NN + mn + tid*4));
            CP_COMMIT();
            CP_WAIT1();          // tile t's copy complete; t+1 still in flight
        } else {
            CP_WAIT0();
        }
        __syncthreads();

        // MMA: 16 rows (this warp) x 128 cols, K = 192
        float acc[16][4];
        #pragma unroll
        for (int i = 0; i < 16; i++)
            #pragma unroll
            for (int j = 0; j < 4; j++) acc[i][j] = 0.f;

        const uint32_t bbase = sb + (cur ? SM_B1 : SM_B0) + baddr_row;
        #pragma unroll 2
        for (int ks = 0; ks < 12; ks++) {
            uint32_t a0, a1, a2, a3;
            asm volatile("ldmatrix.sync.aligned.m8n8.x4.shared.b16 {%0,%1,%2,%3}, [%4];"
                : "=r"(a0), "=r"(a1), "=r"(a2), "=r"(a3)
                : "r"(aaddr0 + (uint32_t)(ks*32)));
            const uint32_t bbk = bbase + (uint32_t)(ks*32);
            #pragma unroll
            for (int ct = 0; ct < 8; ct++) {
                uint32_t b0, b1, b2, b3;
                asm volatile("ldmatrix.sync.aligned.m8n8.x4.shared.b16 {%0,%1,%2,%3}, [%4];"
                    : "=r"(b0), "=r"(b1), "=r"(b2), "=r"(b3)
                    : "r"(bbk + (uint32_t)(ct*16*400)));
                asm volatile("mma.sync.aligned.m16n8k16.row.col.f32.bf16.bf16.f32 "
                    "{%0,%1,%2,%3},{%4,%5,%6,%7},{%8,%9},{%0,%1,%2,%3};"
                    : "+f"(acc[2*ct][0]), "+f"(acc[2*ct][1]),
                      "+f"(acc[2*ct][2]), "+f"(acc[2*ct][3])
                    : "r"(a0), "r"(a1), "r"(a2), "r"(a3), "r"(b0), "r"(b1));
                asm volatile("mma.sync.aligned.m16n8k16.row.col.f32.bf16.bf16.f32 "
                    "{%0,%1,%2,%3},{%4,%5,%6,%7},{%8,%9},{%0,%1,%2,%3};"
                    : "+f"(acc[2*ct+1][0]), "+f"(acc[2*ct+1][1]),
                      "+f"(acc[2*ct+1][2]), "+f"(acc[2*ct+1][3])
                    : "r"(a0), "r"(a1), "r"(a2), "r"(a3), "r"(b2), "r"(b3));
            }
        }

        // stage criterion = sq[m] - 2*dot
        {
            const int rw = w*16 + (lane >> 2);
            const int cb = (lane & 3) * 2;
            const float* sqc = sqs + cur*128;
            #pragma unroll
            for (int i = 0; i < 16; i++) {
                int col = i*8 + cb;
                float s0 = sqc[col], s1 = sqc[col+1];
                *(float2*)&sD[rw*130 + col] =
                    make_float2(fmaf(-2.f, acc[i][0], s0), fmaf(-2.f, acc[i][1], s1));
                *(float2*)&sD[(rw+8)*130 + col] =
                    make_float2(fmaf(-2.f, acc[i][2], s0), fmaf(-2.f, acc[i][3], s1));
            }
        }
        __syncthreads();

        // scan: thread owns half a row, running top-20 over its half of cols
        {
            const float* row = &sD[srow*130 + cbase];
            const int mb = m0 + cbase;
            #pragma unroll 4
            for (int c = 0; c < 64; c++)
                topk_insert(best, bidx, row[c], mb + c);
        }
        __syncthreads();
    }

    // merge the two per-row half-lists (each sorted ascending)
    float* mbf = (float*)(smem + SM_D);
    int*   mbi = (int*)  (smem + SM_D + 256*KNN*4);
    #pragma unroll
    for (int j = 0; j < KNN; j++) { mbf[tid*KNN + j] = best[j]; mbi[tid*KNN + j] = bidx[j]; }
    __syncthreads();
    if (tid < 128) {
        const int ia = tid*KNN, ib = (tid + 128)*KNN;
        int na = 0, nb = 0;
        int* op = g_idx + (b*NN + r0 + tid)*KNN;
        #pragma unroll
        for (int j = 0; j < KNN; j++) {
            float va = mbf[ia + na], vb = mbf[ib + nb];
            if (va <= vb) { op[j] = mbi[ia + na]; na++; }
            else          { op[j] = mbi[ib + nb]; nb++; }
        }
    }
}

// ---------------- kernel 3: gather-max + h + BN partial sums -------------------
__global__ __launch_bounds__(256) void hmax_kernel()
{
    int tid = threadIdx.x;
    int warp = tid >> 5, lane = tid & 31;
    int b = blockIdx.y;
    int nbase = blockIdx.x * 256 + warp * 32;
    const float* yb = g_y + b*NN*OO;

    float s0 = 0.f, s1 = 0.f, q0 = 0.f, q1 = 0.f;
    for (int i = 0; i < 32; i++) {
        int n = nbase + i;
        const int* ip = g_idx + (b*NN + n)*KNN;
        float m0v = -3.4e38f, m1v = -3.4e38f;
        #pragma unroll
        for (int k = 0; k < KNN; k++) {
            int m = ip[k];
            const float* yr = yb + m*OO;
            m0v = fmaxf(m0v, yr[lane]);
            m1v = fmaxf(m1v, yr[lane + 32]);
        }
        const float* zr = g_z + (b*NN + n)*OO;
        float h0 = zr[lane]      + m0v;
        float h1 = zr[lane + 32] + m1v;
        g_h[(b*NN + n)*OO + lane]      = h0;
        g_h[(b*NN + n)*OO + lane + 32] = h1;
        s0 += h0; s1 += h1;
        q0 = fmaf(h0, h0, q0); q1 = fmaf(h1, h1, q1);
    }

    __shared__ float ps[8][64], pq[8][64];
    ps[warp][lane]      = s0; ps[warp][lane + 32] = s1;
    pq[warp][lane]      = q0; pq[warp][lane + 32] = q1;
    __syncthreads();
    if (tid < 64) {
        float S = 0.f, Q = 0.f;
        #pragma unroll
        for (int wr = 0; wr < 8; wr++) { S += ps[wr][tid]; Q += pq[wr][tid]; }
        int blk = b*16 + blockIdx.x;
        g_psum[blk*64 + tid] = S;
        g_psq [blk*64 + tid] = Q;
    }
}

// ---------------- kernel 4: deterministic fp64 stats reduce --------------------
__global__ __launch_bounds__(1024) void stats_kernel(const float* __restrict__ gamma,
                                                     const float* __restrict__ beta)
{
    __shared__ double sS[1024], sQ[1024];
    int ch = threadIdx.x & 63;
    int sl = threadIdx.x >> 6;        // 16 slices per channel
    double S = 0.0, Q = 0.0;
    #pragma unroll
    for (int i = sl; i < 128; i += 16) {
        S += (double)g_psum[i*64 + ch];
        Q += (double)g_psq [i*64 + ch];
    }
    sS[threadIdx.x] = S; sQ[threadIdx.x] = Q;
    __syncthreads();
    if (sl == 0) {
        double St = 0.0, Qt = 0.0;
        #pragma unroll
        for (int k = 0; k < 16; k++) { St += sS[k*64 + ch]; Qt += sQ[k*64 + ch]; }
        double cnt  = (double)(BB * NN);
        double mean = St / cnt;
        double var  = Qt / cnt - mean * mean;
        float inv = (float)(1.0 / sqrt(var + 1e-5));
        float a = gamma[ch] * inv;
        g_a  [ch] = a;
        g_bb2[ch] = beta[ch] - (float)mean * a;
    }
}

// ---------------- kernel 5: BN affine + exact GELU + transpose -----------------
__global__ __launch_bounds__(256) void final_kernel(float* __restrict__ out)
{
    __shared__ float t[64][65];
    int tid = threadIdx.x;
    int b = blockIdx.y;
    int n0 = blockIdx.x * 64;
    const float* hb = g_h + b*NN*OO;

    #pragma unroll
    for (int it = 0; it < 16; it++) {
        int idx = it*256 + tid;
        int nl = idx >> 6, o = idx & 63;
        t[nl][o] = hb[(n0 + nl)*OO + o];
    }
    __syncthreads();

    float* ob = out + b*OO*NN;
    #pragma unroll
    for (int it = 0; it < 16; it++) {
        int idx = it*256 + tid;
        int o = idx >> 6, nl = idx & 63;
        float v = t[nl][o] * g_a[o] + g_bb2[o];
        ob[o*NN + n0 + nl] = 0.5f * v * (1.f + erff(v * 0.70710678118654752f));
    }
}

// ---------------- launch --------------------------------------------------------
extern "C" void kernel_launch(void* const* d_in, const int* in_sizes, int n_in,
                              void* d_out, int out_size)
{
    const float* x     = (const float*)d_in[0];
    const float* w     = (const float*)d_in[1];
    const float* gamma = (const float*)d_in[2];
    const float* beta  = (const float*)d_in[3];
    float* out = (float*)d_out;

    cudaFuncSetAttribute(knn_kernel, cudaFuncAttributeMaxDynamicSharedMemorySize, SM_TOT);

    prep_kernel <<<dim3(NN/128, BB), 128>>>(x, w);
    knn_kernel  <<<dim3(NN/128, BB), 256, SM_TOT>>>();
    hmax_kernel <<<dim3(NN/256, BB), 256>>>();
    stats_kernel<<<1, 1024>>>(gamma, beta);
    final_kernel<<<dim3(NN/64, BB), 256>>>(out);
}

// round 7
// speedup vs baseline: 1.6377x; 1.0288x over previous
#include <cuda_runtime.h>
#include <cuda_bf16.h>
#include <stdint.h>
#include <math.h>

#define BB   8
#define NN   4096
#define DD   64
#define KNN  20
#define OO   64

// ---------------- scratch (__device__ globals: allocation-free) ----------------
__device__ float g_sq[BB*NN];
__device__ float g_y [BB*NN*OO];
__device__ float g_z [BB*NN*OO];
__device__ int   g_idx[BB*NN*KNN];
__device__ float g_h [BB*NN*OO];
__device__ float g_psum[128*OO];
__device__ float g_psq [128*OO];
__device__ float g_a [OO];
__device__ float g_bb2[OO];
__device__ float g_dummy;
// bf16x3 split layouts, k-major per point, K=192:
//   A' = [hi | lo | hi]   B' = [hi | hi | lo]   (dot(A',B') = hh + lh + hl)
__device__ __nv_bfloat16 g_xa[(size_t)BB*NN*192];
__device__ __nv_bfloat16 g_xb[(size_t)BB*NN*192];

__device__ __forceinline__ uint32_t smem_u32(const void* p) {
    uint32_t a;
    asm("{ .reg .u64 t; cvta.to.shared.u64 t, %1; cvt.u32.u64 %0, t; }" : "=r"(a) : "l"(p));
    return a;
}
__device__ __forceinline__ uint32_t pack_bf2(__nv_bfloat16 a, __nv_bfloat16 b) {
    return (uint32_t)__bfloat16_as_ushort(a) | ((uint32_t)__bfloat16_as_ushort(b) << 16);
}
__device__ __forceinline__ void cp16(uint32_t dst, const void* src) {
    asm volatile("cp.async.cg.shared.global [%0], [%1], 16;" :: "r"(dst), "l"(src) : "memory");
}
#define CP_COMMIT() asm volatile("cp.async.commit_group;" ::: "memory")
#define CP_WAIT0()  asm volatile("cp.async.wait_group 0;" ::: "memory")
#define CP_WAIT1()  asm volatile("cp.async.wait_group 1;" ::: "memory")

// ---------------- dummy: steers ncu's skip-5 capture onto knn ------------------
__global__ void dummy_kernel()
{
    if (threadIdx.x > 1000) g_dummy = 1.f;   // never true (32 threads)
}

// ---------------- kernel 1: sumsq, y, z, and bf16x3 split layouts --------------
__global__ __launch_bounds__(128) void prep_kernel(const float* __restrict__ x,
                                                   const float* __restrict__ w)
{
    __shared__ float ws[64*128];
    int tid = threadIdx.x;
    #pragma unroll
    for (int i = 0; i < 64; i++) ws[i*128 + tid] = w[i*128 + tid];
    __syncthreads();

    int b = blockIdx.y;
    int n = blockIdx.x * 128 + tid;
    const float* xb = x + b * (DD*NN);

    float p[DD];
    float sq = 0.f;
    #pragma unroll
    for (int d = 0; d < DD; d++) { p[d] = xb[d*NN + n]; sq = fmaf(p[d], p[d], sq); }
    g_sq[b*NN + n] = sq;

    uint4* pa = (uint4*)(g_xa + (size_t)(b*NN + n)*192);
    uint4* pb = (uint4*)(g_xb + (size_t)(b*NN + n)*192);
    #pragma unroll
    for (int d = 0; d < DD; d += 8) {
        uint32_t hv[4], lv[4];
        #pragma unroll
        for (int j = 0; j < 4; j++) {
            float v0 = p[d + 2*j], v1 = p[d + 2*j + 1];
            __nv_bfloat16 h0 = __float2bfloat16(v0);
            __nv_bfloat16 h1 = __float2bfloat16(v1);
            __nv_bfloat16 l0 = __float2bfloat16(v0 - __bfloat162float(h0));
            __nv_bfloat16 l1 = __float2bfloat16(v1 - __bfloat162float(h1));
            hv[j] = pack_bf2(h0, h1);
            lv[j] = pack_bf2(l0, l1);
        }
        uint4 H = make_uint4(hv[0], hv[1], hv[2], hv[3]);
        uint4 L = make_uint4(lv[0], lv[1], lv[2], lv[3]);
        int c = d >> 3;
        pa[c] = H; pa[8 + c] = L; pa[16 + c] = H;
        pb[c] = H; pb[8 + c] = H; pb[16 + c] = L;
    }

    float* yp = g_y + (b*NN + n)*OO;
    float* zp = g_z + (b*NN + n)*OO;
    #pragma unroll 2
    for (int o = 0; o < OO; o += 4) {
        float ya[4], za[4];
        #pragma unroll
        for (int j = 0; j < 4; j++) { ya[j] = 0.f; za[j] = 0.f; }
        #pragma unroll
        for (int d = 0; d < DD; d++) {
            float pd = p[d];
            #pragma unroll
            for (int j = 0; j < 4; j++) {
                float w1 = ws[(o+j)*128 + d];
                float w2 = ws[(o+j)*128 + 64 + d];
                ya[j] = fmaf(pd, w1, ya[j]);
                za[j] = fmaf(pd, w2 - w1, za[j]);
            }
        }
        *(float4*)&yp[o] = make_float4(ya[0], ya[1], ya[2], ya[3]);
        *(float4*)&zp[o] = make_float4(za[0], za[1], za[2], za[3]);
    }
}

// ---------------- kernel 2: HMMA Gram + cp.async pipeline + top-20 -------------
__device__ __forceinline__ void topk_insert(float (&best)[KNN], int (&bidx)[KNN],
                                            float c, int m)
{
    if (c < best[KNN-1]) {
        best[KNN-1] = c; bidx[KNN-1] = m;
        #pragma unroll
        for (int t = KNN-1; t > 0; --t) {
            if (best[t-1] > best[t]) {
                float tf = best[t-1]; best[t-1] = best[t]; best[t] = tf;
                int   ti = bidx[t-1]; bidx[t-1] = bidx[t]; bidx[t] = ti;
            }
        }
    }
}

// smem layout: bf16 tiles use 400B row stride (conflict-free ldmatrix)
#define SM_A   0
#define SM_B0  51200
#define SM_B1  102400
#define SM_SQ  153600            // float sqs[2][128]
#define SM_D   154624            // float sD[128][130]; aliased for merge lists
#define SM_TOT 221184

__global__ __launch_bounds__(256, 1) void knn_kernel()
{
    extern __shared__ char smem[];
    const uint32_t sb = smem_u32(smem);
    float* sD  = (float*)(smem + SM_D);
    float* sqs = (float*)(smem + SM_SQ);

    const int tid  = threadIdx.x;
    const int lane = tid & 31;
    const int w    = tid >> 5;
    const int b    = blockIdx.y;
    const int r0   = blockIdx.x * 128;

    // issue async copy of B tile 0 + sq 0 first (deepest prefetch)
    {
        const char* gb = (const char*)(g_xb + (size_t)(b*NN)*192);
        #pragma unroll 4
        for (int i = tid; i < 128*24; i += 256) {
            int p = i / 24, c = i % 24;
            cp16(sb + SM_B0 + (uint32_t)(p*400 + c*16), gb + p*384 + c*16);
        }
        if (tid < 32) cp16(sb + SM_SQ + (uint32_t)(tid*16), (const char*)(g_sq + b*NN + tid*4));
        CP_COMMIT();
    }
    // A' rows r0..r0+127 (384B/row) -> smem (400B/row), plain copy (overlaps cp.async)
    {
        const char* ga = (const char*)(g_xa + (size_t)(b*NN + r0)*192);
        #pragma unroll 4
        for (int i = tid; i < 128*24; i += 256) {
            int p = i / 24, c = i % 24;
            *(uint4*)(smem + SM_A + p*400 + c*16) = *(const uint4*)(ga + p*384 + c*16);
        }
    }

    float best[KNN];
    int   bidx[KNN];
    #pragma unroll
    for (int j = 0; j < KNN; j++) { best[j] = 3.4e38f; bidx[j] = 0; }

    const int half  = tid >> 7;          // 0 or 1
    const int srow  = tid & 127;
    const int cbase = half * 64;

    // 4x2 warp tiling: warp owns rows rg*32..+31, cols cg*64..+63
    const int rg = w >> 1;
    const int cg = w & 1;

    // ldmatrix lane addressing: mm = matrix index (l>>3), rr = l&7
    const int mm = lane >> 3, rr = lane & 7;
    // A: mm bit0 -> row+8, bit1 -> k+8
    const uint32_t aaddr0 = sb + SM_A
        + (uint32_t)((rg*32 + ((mm & 1) << 3) + rr) * 400)
        + (uint32_t)(((mm & 2) ? 8 : 0) * 2);
    // B: mm bit1 -> col(point)+8, bit0 -> k+8; warp's col window = cg*64
    const uint32_t baddr_row = (uint32_t)((cg*64 + ((mm & 2) ? 8 : 0) + rr) * 400)
                             + (uint32_t)(((mm & 1) ? 8 : 0) * 2);

    for (int t = 0; t < 32; t++) {
        const int cur = t & 1;
        const int nxt = cur ^ 1;
        const int m0  = t * 128;

        // prefetch B tile t+1 + sq into the other buffer (async, overlapped)
        if (t + 1 < 32) {
            const int mn = m0 + 128;
            const char* gb = (const char*)(g_xb + (size_t)(b*NN + mn)*192);
            const uint32_t bdst = sb + (nxt ? SM_B1 : SM_B0);
            #pragma unroll 4
            for (int i = tid; i < 128*24; i += 256) {
                int p = i / 24, c = i % 24;
                cp16(bdst + (uint32_t)(p*400 + c*16), gb + p*384 + c*16);
            }
            if (tid < 32) cp16(sb + SM_SQ + (uint32_t)(nxt*512 + tid*16),
                               (const char*)(g_sq + b*NN + mn + tid*4));
            CP_COMMIT();
            CP_WAIT1();          // tile t's copy complete; t+1 still in flight
        } else {
            CP_WAIT0();
        }
        __syncthreads();

        // MMA: 32 rows x 64 cols per warp, K = 192
        float acc[2][8][4];
        #pragma unroll
        for (int rt = 0; rt < 2; rt++)
            #pragma unroll
            for (int i = 0; i < 8; i++)
                #pragma unroll
                for (int j = 0; j < 4; j++) acc[rt][i][j] = 0.f;

        const uint32_t bbase = sb + (cur ? SM_B1 : SM_B0) + baddr_row;
        #pragma unroll 2
        for (int ks = 0; ks < 12; ks++) {
            uint32_t a0[4], a1[4];
            asm volatile("ldmatrix.sync.aligned.m8n8.x4.shared.b16 {%0,%1,%2,%3}, [%4];"
                : "=r"(a0[0]), "=r"(a0[1]), "=r"(a0[2]), "=r"(a0[3])
                : "r"(aaddr0 + (uint32_t)(ks*32)));
            asm volatile("ldmatrix.sync.aligned.m8n8.x4.shared.b16 {%0,%1,%2,%3}, [%4];"
                : "=r"(a1[0]), "=r"(a1[1]), "=r"(a1[2]), "=r"(a1[3])
                : "r"(aaddr0 + (uint32_t)(16*400 + ks*32)));
            const uint32_t bbk = bbase + (uint32_t)(ks*32);
            #pragma unroll
            for (int bq = 0; bq < 4; bq++) {
                uint32_t b0, b1, b2, b3;
                asm volatile("ldmatrix.sync.aligned.m8n8.x4.shared.b16 {%0,%1,%2,%3}, [%4];"
                    : "=r"(b0), "=r"(b1), "=r"(b2), "=r"(b3)
                    : "r"(bbk + (uint32_t)(bq*16*400)));
                asm volatile("mma.sync.aligned.m16n8k16.row.col.f32.bf16.bf16.f32 "
                    "{%0,%1,%2,%3},{%4,%5,%6,%7},{%8,%9},{%0,%1,%2,%3};"
                    : "+f"(acc[0][2*bq][0]), "+f"(acc[0][2*bq][1]),
                      "+f"(acc[0][2*bq][2]), "+f"(acc[0][2*bq][3])
                    : "r"(a0[0]), "r"(a0[1]), "r"(a0[2]), "r"(a0[3]), "r"(b0), "r"(b1));
                asm volatile("mma.sync.aligned.m16n8k16.row.col.f32.bf16.bf16.f32 "
                    "{%0,%1,%2,%3},{%4,%5,%6,%7},{%8,%9},{%0,%1,%2,%3};"
                    : "+f"(acc[0][2*bq+1][0]), "+f"(acc[0][2*bq+1][1]),
                      "+f"(acc[0][2*bq+1][2]), "+f"(acc[0][2*bq+1][3])
                    : "r"(a0[0]), "r"(a0[1]), "r"(a0[2]), "r"(a0[3]), "r"(b2), "r"(b3));
                asm volatile("mma.sync.aligned.m16n8k16.row.col.f32.bf16.bf16.f32 "
                    "{%0,%1,%2,%3},{%4,%5,%6,%7},{%8,%9},{%0,%1,%2,%3};"
                    : "+f"(acc[1][2*bq][0]), "+f"(acc[1][2*bq][1]),
                      "+f"(acc[1][2*bq][2]), "+f"(acc[1][2*bq][3])
                    : "r"(a1[0]), "r"(a1[1]), "r"(a1[2]), "r"(a1[3]), "r"(b0), "r"(b1));
                asm volatile("mma.sync.aligned.m16n8k16.row.col.f32.bf16.bf16.f32 "
                    "{%0,%1,%2,%3},{%4,%5,%6,%7},{%8,%9},{%0,%1,%2,%3};"
                    : "+f"(acc[1][2*bq+1][0]), "+f"(acc[1][2*bq+1][1]),
                      "+f"(acc[1][2*bq+1][2]), "+f"(acc[1][2*bq+1][3])
                    : "r"(a1[0]), "r"(a1[1]), "r"(a1[2]), "r"(a1[3]), "r"(b2), "r"(b3));
            }
        }

        // stage criterion = sq[m] - 2*dot
        {
            const int rw0 = rg*32 + (lane >> 2);
            const int cb  = (lane & 3) * 2;
            const float* sqc = sqs + cur*128;
            #pragma unroll
            for (int rt = 0; rt < 2; rt++) {
                #pragma unroll
                for (int ct = 0; ct < 8; ct++) {
                    int col = cg*64 + ct*8 + cb;
                    float s0 = sqc[col], s1 = sqc[col+1];
                    int rw = rw0 + rt*16;
                    *(float2*)&sD[rw*130 + col] =
                        make_float2(fmaf(-2.f, acc[rt][ct][0], s0), fmaf(-2.f, acc[rt][ct][1], s1));
                    *(float2*)&sD[(rw+8)*130 + col] =
                        make_float2(fmaf(-2.f, acc[rt][ct][2], s0), fmaf(-2.f, acc[rt][ct][3], s1));
                }
            }
        }
        __syncthreads();

        // scan: thread owns half a row, running top-20 over its half of cols
        {
            const float* row = &sD[srow*130 + cbase];
            const int mb = m0 + cbase;
            #pragma unroll 4
            for (int c = 0; c < 64; c++)
                topk_insert(best, bidx, row[c], mb + c);
        }
        __syncthreads();
    }

    // merge the two per-row half-lists (each sorted ascending)
    float* mbf = (float*)(smem + SM_D);
    int*   mbi = (int*)  (smem + SM_D + 256*KNN*4);
    #pragma unroll
    for (int j = 0; j < KNN; j++) { mbf[tid*KNN + j] = best[j]; mbi[tid*KNN + j] = bidx[j]; }
    __syncthreads();
    if (tid < 128) {
        const int ia = tid*KNN, ib = (tid + 128)*KNN;
        int na = 0, nb = 0;
        int* op = g_idx + (b*NN + r0 + tid)*KNN;
        #pragma unroll
        for (int j = 0; j < KNN; j++) {
            float va = mbf[ia + na], vb = mbf[ib + nb];
            if (va <= vb) { op[j] = mbi[ia + na]; na++; }
            else          { op[j] = mbi[ib + nb]; nb++; }
        }
    }
}

// ---------------- kernel 3: gather-max + h + BN partial sums -------------------
__global__ __launch_bounds__(256) void hmax_kernel()
{
    int tid = threadIdx.x;
    int warp = tid >> 5, lane = tid & 31;
    int b = blockIdx.y;
    int nbase = blockIdx.x * 256 + warp * 32;
    const float* yb = g_y + b*NN*OO;

    float s0 = 0.f, s1 = 0.f, q0 = 0.f, q1 = 0.f;
    for (int i = 0; i < 32; i++) {
        int n = nbase + i;
        const int* ip = g_idx + (b*NN + n)*KNN;
        float m0v = -3.4e38f, m1v = -3.4e38f;
        #pragma unroll
        for (int k = 0; k < KNN; k++) {
            int m = ip[k];
            const float* yr = yb + m*OO;
            m0v = fmaxf(m0v, yr[lane]);
            m1v = fmaxf(m1v, yr[lane + 32]);
        }
        const float* zr = g_z + (b*NN + n)*OO;
        float h0 = zr[lane]      + m0v;
        float h1 = zr[lane + 32] + m1v;
        g_h[(b*NN + n)*OO + lane]      = h0;
        g_h[(b*NN + n)*OO + lane + 32] = h1;
        s0 += h0; s1 += h1;
        q0 = fmaf(h0, h0, q0); q1 = fmaf(h1, h1, q1);
    }

    __shared__ float ps[8][64], pq[8][64];
    ps[warp][lane]      = s0; ps[warp][lane + 32] = s1;
    pq[warp][lane]      = q0; pq[warp][lane + 32] = q1;
    __syncthreads();
    if (tid < 64) {
        float S = 0.f, Q = 0.f;
        #pragma unroll
        for (int wr = 0; wr < 8; wr++) { S += ps[wr][tid]; Q += pq[wr][tid]; }
        int blk = b*16 + blockIdx.x;
        g_psum[blk*64 + tid] = S;
        g_psq [blk*64 + tid] = Q;
    }
}

// ---------------- kernel 4: deterministic fp64 stats reduce --------------------
__global__ __launch_bounds__(1024) void stats_kernel(const float* __restrict__ gamma,
                                                     const float* __restrict__ beta)
{
    __shared__ double sS[1024], sQ[1024];
    int ch = threadIdx.x & 63;
    int sl = threadIdx.x >> 6;        // 16 slices per channel
    double S = 0.0, Q = 0.0;
    #pragma unroll
    for (int i = sl; i < 128; i += 16) {
        S += (double)g_psum[i*64 + ch];
        Q += (double)g_psq [i*64 + ch];
    }
    sS[threadIdx.x] = S; sQ[threadIdx.x] = Q;
    __syncthreads();
    if (sl == 0) {
        double St = 0.0, Qt = 0.0;
        #pragma unroll
        for (int k = 0; k < 16; k++) { St += sS[k*64 + ch]; Qt += sQ[k*64 + ch]; }
        double cnt  = (double)(BB * NN);
        double mean = St / cnt;
        double var  = Qt / cnt - mean * mean;
        float inv = (float)(1.0 / sqrt(var + 1e-5));
        float a = gamma[ch] * inv;
        g_a  [ch] = a;
        g_bb2[ch] = beta[ch] - (float)mean * a;
    }
}

// ---------------- kernel 5: BN affine + exact GELU + transpose -----------------
__global__ __launch_bounds__(256) void final_kernel(float* __restrict__ out)
{
    __shared__ float t[64][65];
    int tid = threadIdx.x;
    int b = blockIdx.y;
    int n0 = blockIdx.x * 64;
    const float* hb = g_h + b*NN*OO;

    #pragma unroll
    for (int it = 0; it < 16; it++) {
        int idx = it*256 + tid;
        int nl = idx >> 6, o = idx & 63;
        t[nl][o] = hb[(n0 + nl)*OO + o];
    }
    __syncthreads();

    float* ob = out + b*OO*NN;
    #pragma unroll
    for (int it = 0; it < 16; it++) {
        int idx = it*256 + tid;
        int o = idx >> 6, nl = idx & 63;
        float v = t[nl][o] * g_a[o] + g_bb2[o];
        ob[o*NN + n0 + nl] = 0.5f * v * (1.f + erff(v * 0.70710678118654752f));
    }
}

// ---------------- launch --------------------------------------------------------
extern "C" void kernel_launch(void* const* d_in, const int* in_sizes, int n_in,
                              void* d_out, int out_size)
{
    const float* x     = (const float*)d_in[0];
    const float* w     = (const float*)d_in[1];
    const float* gamma = (const float*)d_in[2];
    const float* beta  = (const float*)d_in[3];
    float* out = (float*)d_out;

    cudaFuncSetAttribute(knn_kernel, cudaFuncAttributeMaxDynamicSharedMemorySize, SM_TOT);

    prep_kernel <<<dim3(NN/128, BB), 128>>>(x, w);
    dummy_kernel<<<1, 32>>>();
    dummy_kernel<<<1, 32>>>();
    knn_kernel  <<<dim3(NN/128, BB), 256, SM_TOT>>>();
    hmax_kernel <<<dim3(NN/256, BB), 256>>>();
    stats_kernel<<<1, 1024>>>(gamma, beta);
    final_kernel<<<dim3(NN/64, BB), 256>>>(out);
}